// round 8
// baseline (speedup 1.0000x reference)
#include <cuda_runtime.h>
#include <cuda_fp16.h>

#define NN   50000
#define EE   800000
#define INC  128
#define OUTC 32
#define HH   4
#define EDIM 16
#define HO   128          // H*OUT
#define ENF  (EE + NN)    // edges + self loops = 850000 (divisible by 16)
#define NBATCH (ENF / 16) // 53125 mma warp batches
#define SLOPE 0.2f
#define SCHUNK 49         // ceil(NN/1024)

// ---------------- scratch (device globals; no allocation allowed) ----------
__device__ uint2    g_xlh[(size_t)NN * 32];      // x@W_l+b_l, fp16 (12.8 MB)
__device__ float    g_xr [(size_t)NN * HO];      // x@W_r+b_r, fp32 (25.6 MB)
__device__ int      g_degi[NN];                  // in-degree (int)
__device__ float    g_asum[(size_t)NN * EDIM];   // scatter-sum of edge attrs
__device__ int      g_off[NN + 1];               // CSR offsets
__device__ int      g_cur[NN];                   // CSR fill cursors
__device__ int2     g_csr[EE];                   // (src, edge-id) sorted by tgt
__device__ uint2    g_eh[(size_t)ENF * 32];      // E row-major fp16 (217.6 MB)

// ---------------- helpers --------------------------------------------------
__device__ __forceinline__ float lrelu(float v) { return v > 0.f ? v : SLOPE * v; }

__device__ __forceinline__ void red_add_v4(float4* addr, float4 v) {
    asm volatile("red.global.add.v4.f32 [%0], {%1,%2,%3,%4};"
                 :: "l"(addr), "f"(v.x), "f"(v.y), "f"(v.z), "f"(v.w)
                 : "memory");
}

// pack two f32 into f16x2: lo -> bits[15:0], hi -> bits[31:16]
__device__ __forceinline__ unsigned pack_h2(float hi, float lo) {
    unsigned r;
    asm("cvt.rn.f16x2.f32 %0, %1, %2;" : "=r"(r) : "f"(hi), "f"(lo));
    return r;
}

// packed fp32x2 FMA (Blackwell FFMA2 — only reachable via PTX)
__device__ __forceinline__ unsigned long long pk2(float lo, float hi) {
    unsigned long long r;
    asm("mov.b64 %0, {%1, %2};" : "=l"(r) : "f"(lo), "f"(hi));
    return r;
}
__device__ __forceinline__ void fma2(unsigned long long& d, unsigned long long a,
                                     unsigned long long b, unsigned long long c) {
    asm("fma.rn.f32x2 %0, %1, %2, %3;" : "=l"(d) : "l"(a), "l"(b), "l"(c));
}
__device__ __forceinline__ float2 upk2(unsigned long long v) {
    float2 f;
    asm("mov.b64 {%0, %1}, %2;" : "=f"(f.x), "=f"(f.y) : "l"(v));
    return f;
}

// ---------------- kernel 1: zero scratch -----------------------------------
__global__ void zero_kernel() {
    int i = blockIdx.x * blockDim.x + threadIdx.x;
    int stride = gridDim.x * blockDim.x;
    for (int j = i; j < NN * EDIM; j += stride) g_asum[j] = 0.f;
    for (int j = i; j < NN; j += stride) g_degi[j] = 0;
}

// ---------------- kernel 2: degree + attr scatter-sum ----------------------
__global__ void deg_attr_kernel(const int* __restrict__ ei,
                                const float* __restrict__ eattr) {
    int e = blockIdx.x * blockDim.x + threadIdx.x;
    if (e >= EE) return;
    int t = ei[EE + e];
    const float4* a4 = (const float4*)&eattr[(long)e * EDIM];
    float4* dst = &((float4*)g_asum)[(long)t * 4];
#pragma unroll
    for (int q = 0; q < 4; q++) red_add_v4(&dst[q], a4[q]);
    atomicAdd(&g_degi[t], 1);
}

// ---------------- kernel 3: CSR offset scan (single block) -----------------
__global__ void scan_kernel() {
    __shared__ int ssum[1024];
    int tid = threadIdx.x;
    int start = tid * SCHUNK;
    int end = min(start + SCHUNK, NN);
    int tot = 0;
    for (int n = start; n < end; n++) tot += g_degi[n];
    ssum[tid] = tot;
    __syncthreads();
    for (int d = 1; d < 1024; d <<= 1) {
        int v = (tid >= d) ? ssum[tid - d] : 0;
        __syncthreads();
        ssum[tid] += v;
        __syncthreads();
    }
    int run = ssum[tid] - tot;   // exclusive prefix
    for (int n = start; n < end; n++) {
        g_off[n] = run;
        g_cur[n] = run;
        run += g_degi[n];
    }
    if (tid == 0) g_off[NN] = EE;
}

// ---------------- kernel 4: CSR scatter -------------------------------------
__global__ void scatter_kernel(const int* __restrict__ ei) {
    int e = blockIdx.x * blockDim.x + threadIdx.x;
    if (e >= EE) return;
    int s = ei[e], t = ei[EE + e];
    int pos = atomicAdd(&g_cur[t], 1);
    g_csr[pos] = make_int2(s, e);
}

// ---------------- kernel 5: x_l / x_r GEMMs with FFMA2 ---------------------
// x_l stored fp16 (gathered per-edge later), x_r stored fp32 (read per-node).
__global__ void gemm_xlr(const float* __restrict__ x,
                         const float* __restrict__ Wl, const float* __restrict__ bl,
                         const float* __restrict__ Wr, const float* __restrict__ br) {
    __shared__ float xs[64][INC];
    int row0 = blockIdx.x * 64;
    int tid = threadIdx.x;

    const float4* x4 = (const float4*)x;
    for (int i = tid; i < 64 * 32; i += 256) {
        int r = i >> 5, c = i & 31;
        float4 v = make_float4(0.f, 0.f, 0.f, 0.f);
        if (row0 + r < NN) v = x4[(long)(row0 + r) * 32 + c];
        ((float4*)xs[r])[c] = v;
    }
    __syncthreads();

    int tx = tid & 31, ty = tid >> 5;
    unsigned long long accL[8][2], accR[8][2];
    unsigned long long z2 = pk2(0.f, 0.f);
#pragma unroll
    for (int r = 0; r < 8; r++) {
        accL[r][0] = z2; accL[r][1] = z2;
        accR[r][0] = z2; accR[r][1] = z2;
    }
    const float4* Wl4 = (const float4*)Wl;
    const float4* Wr4 = (const float4*)Wr;
    for (int k = 0; k < INC; k++) {
        float4 wl = Wl4[k * 32 + tx];
        float4 wr = Wr4[k * 32 + tx];
        unsigned long long wl0 = pk2(wl.x, wl.y), wl1 = pk2(wl.z, wl.w);
        unsigned long long wr0 = pk2(wr.x, wr.y), wr1 = pk2(wr.z, wr.w);
#pragma unroll
        for (int r = 0; r < 8; r++) {
            float xv = xs[ty + r * 8][k];
            unsigned long long xv2 = pk2(xv, xv);
            fma2(accL[r][0], xv2, wl0, accL[r][0]);
            fma2(accL[r][1], xv2, wl1, accL[r][1]);
            fma2(accR[r][0], xv2, wr0, accR[r][0]);
            fma2(accR[r][1], xv2, wr1, accR[r][1]);
        }
    }
    float4 blv = ((const float4*)bl)[tx];
    float4 brv = ((const float4*)br)[tx];
#pragma unroll
    for (int r = 0; r < 8; r++) {
        int row = row0 + ty + r * 8;
        if (row < NN) {
            float2 l0 = upk2(accL[r][0]), l1 = upk2(accL[r][1]);
            float2 r0 = upk2(accR[r][0]), r1 = upk2(accR[r][1]);
            uint2 xo;
            xo.x = pack_h2(l0.y + blv.y, l0.x + blv.x);
            xo.y = pack_h2(l1.y + blv.w, l1.x + blv.z);
            g_xlh[(size_t)row * 32 + tx] = xo;
            ((float4*)g_xr)[(long)row * 32 + tx] =
                make_float4(r0.x + brv.x, r0.y + brv.y, r1.x + brv.z, r1.y + brv.w);
        }
    }
}

// ---------------- kernel 6: edge projection via tensor cores ---------------
// Warp computes 16 rows x 128 cols of E = attr_full @ W_e with 16x
// mma.sync.m16n8k16. Fragments staged through padded smem (stride 68,
// conflict-free), then coalesced row-major fp16 stores.
__global__ void __launch_bounds__(256)
egemm_mma_kernel(const float* __restrict__ eattr,
                 const float* __restrict__ We) {
    __shared__ unsigned es[8][16 * 68];
    int lane = threadIdx.x & 31;
    int w = threadIdx.x >> 5;
    long warpid = (long)blockIdx.x * 8 + w;
    if (warpid >= NBATCH) return;
    int grp = lane >> 2, ctg = lane & 3;

    unsigned b0[16], b1[16];
#pragma unroll
    for (int t = 0; t < 16; t++) {
        int col = t * 8 + grp;
        float x0 = __ldg(&We[(2 * ctg) * HO + col]);
        float x1 = __ldg(&We[(2 * ctg + 1) * HO + col]);
        float x2 = __ldg(&We[(2 * ctg + 8) * HO + col]);
        float x3 = __ldg(&We[(2 * ctg + 9) * HO + col]);
        b0[t] = pack_h2(x1, x0);
        b1[t] = pack_h2(x3, x2);
    }

    long base = warpid * 16;
    unsigned a0, a1, a2, a3;
    {
        long row = base + grp;
        const float* p; float inv = 1.f;
        if (row < EE) { p = &eattr[row * EDIM]; }
        else { int n = (int)(row - EE); p = &g_asum[(size_t)n * EDIM];
               inv = 1.f / (float)max(g_degi[n], 1); }
        float2 lo = *(const float2*)(p + 2 * ctg);
        float2 hi = *(const float2*)(p + 2 * ctg + 8);
        a0 = pack_h2(lo.y * inv, lo.x * inv);
        a2 = pack_h2(hi.y * inv, hi.x * inv);
    }
    {
        long row = base + grp + 8;
        const float* p; float inv = 1.f;
        if (row < EE) { p = &eattr[row * EDIM]; }
        else { int n = (int)(row - EE); p = &g_asum[(size_t)n * EDIM];
               inv = 1.f / (float)max(g_degi[n], 1); }
        float2 lo = *(const float2*)(p + 2 * ctg);
        float2 hi = *(const float2*)(p + 2 * ctg + 8);
        a1 = pack_h2(lo.y * inv, lo.x * inv);
        a3 = pack_h2(hi.y * inv, hi.x * inv);
    }

    unsigned* sm = es[w];
    float z = 0.f;
#pragma unroll
    for (int t = 0; t < 16; t++) {
        float d0, d1, d2, d3;
        asm volatile(
            "mma.sync.aligned.m16n8k16.row.col.f32.f16.f16.f32 "
            "{%0,%1,%2,%3}, {%4,%5,%6,%7}, {%8,%9}, {%10,%10,%10,%10};"
            : "=f"(d0), "=f"(d1), "=f"(d2), "=f"(d3)
            : "r"(a0), "r"(a1), "r"(a2), "r"(a3),
              "r"(b0[t]), "r"(b1[t]), "f"(z));
        sm[grp * 68 + t * 4 + ctg]       = pack_h2(d1, d0);
        sm[(grp + 8) * 68 + t * 4 + ctg] = pack_h2(d3, d2);
    }
    __syncwarp();

    uint2* dst = &g_eh[(size_t)base * 32];
#pragma unroll
    for (int i = lane; i < 512; i += 32) {
        int r = i >> 5, w2 = i & 31;
        dst[i] = make_uint2(sm[r * 68 + 2 * w2], sm[r * 68 + 2 * w2 + 1]);
    }
}

// ---------------- kernel 7: CSR gather-side fused aggregation --------------
// One warp per target node. acc/den live in registers; no atomics, no
// scratch accumulators. Self-loop processed as extra first iteration.
// Softmax without max-subtraction (alpha identical, scores bounded).
__global__ void __launch_bounds__(256)
csr_gather_kernel(const float* __restrict__ att,
                  const float* __restrict__ bias,
                  float* __restrict__ out) {
    int lane = threadIdx.x & 31;
    int t = blockIdx.x * 8 + (threadIdx.x >> 5);
    if (t >= NN) return;

    float4 xr = ((const float4*)g_xr)[(long)t * 32 + lane];
    float4 av = ((const float4*)att)[lane];

    float4 acc = make_float4(0.f, 0.f, 0.f, 0.f);
    float den = 0.f;
    int beg = g_off[t], end = g_off[t + 1];

    for (int k = beg - 1; k < end; k++) {
        int s, erow;
        if (k < beg) { s = t; erow = EE + t; }          // self-loop
        else { int2 se = __ldg(&g_csr[k]); s = se.x; erow = se.y; }

        uint2 xh = __ldg(&g_xlh[(size_t)s * 32 + lane]);
        float2 x01 = __half22float2(*(__half2*)&xh.x);
        float2 x23 = __half22float2(*(__half2*)&xh.y);
        uint2 ev = __ldg(&g_eh[(size_t)erow * 32 + lane]);
        float2 e01 = __half22float2(*(__half2*)&ev.x);
        float2 e23 = __half22float2(*(__half2*)&ev.y);

        float m0 = lrelu(x01.x + xr.x + e01.x);
        float m1 = lrelu(x01.y + xr.y + e01.y);
        float m2 = lrelu(x23.x + xr.z + e23.x);
        float m3 = lrelu(x23.y + xr.w + e23.y);
        float p = m0 * av.x + m1 * av.y + m2 * av.z + m3 * av.w;
        p += __shfl_xor_sync(0xffffffffu, p, 4);
        p += __shfl_xor_sync(0xffffffffu, p, 2);
        p += __shfl_xor_sync(0xffffffffu, p, 1);

        float ex = __expf(p);
        den += ex;
        acc.x = fmaf(ex, x01.x, acc.x);
        acc.y = fmaf(ex, x01.y, acc.y);
        acc.z = fmaf(ex, x23.x, acc.z);
        acc.w = fmaf(ex, x23.y, acc.w);
    }

    float idn = 1.f / den;           // den > 0 (self-loop always present)
    float4 v = make_float4(acc.x * idn, acc.y * idn, acc.z * idn, acc.w * idn);
    // sum across the 4 heads (lanes L, L+8, L+16, L+24 hold same out-channel)
    v.x += __shfl_xor_sync(0xffffffffu, v.x, 8);
    v.y += __shfl_xor_sync(0xffffffffu, v.y, 8);
    v.z += __shfl_xor_sync(0xffffffffu, v.z, 8);
    v.w += __shfl_xor_sync(0xffffffffu, v.w, 8);
    v.x += __shfl_xor_sync(0xffffffffu, v.x, 16);
    v.y += __shfl_xor_sync(0xffffffffu, v.y, 16);
    v.z += __shfl_xor_sync(0xffffffffu, v.z, 16);
    v.w += __shfl_xor_sync(0xffffffffu, v.w, 16);

    if (lane < 8) {
        float4 bv = ((const float4*)bias)[lane];
        float4 o = make_float4(lrelu(0.25f * v.x + bv.x),
                               lrelu(0.25f * v.y + bv.y),
                               lrelu(0.25f * v.z + bv.z),
                               lrelu(0.25f * v.w + bv.w));
        ((float4*)out)[(long)t * 8 + lane] = o;
    }
}

// ---------------- launch ---------------------------------------------------
extern "C" void kernel_launch(void* const* d_in, const int* in_sizes, int n_in,
                              void* d_out, int out_size) {
    const float* x     = (const float*)d_in[0];
    const int*   ei    = (const int*)  d_in[1];
    const float* eattr = (const float*)d_in[2];
    const float* Wl    = (const float*)d_in[3];
    const float* bl    = (const float*)d_in[4];
    const float* Wr    = (const float*)d_in[5];
    const float* br    = (const float*)d_in[6];
    const float* We    = (const float*)d_in[7];
    const float* att   = (const float*)d_in[8];
    const float* bias  = (const float*)d_in[9];
    float* out = (float*)d_out;

    zero_kernel<<<512, 256>>>();
    deg_attr_kernel<<<(EE + 255) / 256, 256>>>(ei, eattr);
    scan_kernel<<<1, 1024>>>();
    scatter_kernel<<<(EE + 255) / 256, 256>>>(ei);
    gemm_xlr<<<(NN + 63) / 64, 256>>>(x, Wl, bl, Wr, br);
    egemm_mma_kernel<<<(NBATCH + 7) / 8, 256>>>(eattr, We);
    csr_gather_kernel<<<(NN + 7) / 8, 256>>>(att, bias, out);
}

// round 9
// speedup vs baseline: 1.1178x; 1.1178x over previous
#include <cuda_runtime.h>
#include <cuda_fp16.h>

#define NN   50000
#define EE   800000
#define INC  128
#define OUTC 32
#define HH   4
#define EDIM 16
#define HO   128          // H*OUT
#define ENF  (EE + NN)    // edges + self loops = 850000 (divisible by 16)
#define NBATCH (ENF / 16) // 53125 mma warp batches
#define SLOPE 0.2f

// ---------------- scratch (device globals; no allocation allowed) ----------
__device__ uint2    g_xlh[(size_t)NN * 32];      // x@W_l+b_l fp16 (12.8 MB)
__device__ uint2    g_xrh[(size_t)NN * 32];      // x@W_r+b_r fp16 (12.8 MB)
__device__ float    g_deg[NN];                   // in-degree
__device__ float    g_asum[(size_t)NN * EDIM];   // scatter-sum of edge attrs
__device__ float    g_denom[(size_t)NN * HH];    // softmax denominators
__device__ float4   g_accum[(size_t)NN * OUTC];  // sum exp(s)*x_l[src] (25.6 MB)
// E in mma-fragment permuted order: [batch][tile 0..15][sel 0..1][lane 0..31]
__device__ unsigned g_eperm[(size_t)NBATCH * 1024];   // fp16x2 words (217.6 MB)

// ---------------- helpers --------------------------------------------------
__device__ __forceinline__ float lrelu(float v) { return v > 0.f ? v : SLOPE * v; }

__device__ __forceinline__ void red_add_v4(float4* addr, float4 v) {
    asm volatile("red.global.add.v4.f32 [%0], {%1,%2,%3,%4};"
                 :: "l"(addr), "f"(v.x), "f"(v.y), "f"(v.z), "f"(v.w)
                 : "memory");
}

// pack two f32 into f16x2: lo -> bits[15:0], hi -> bits[31:16]
__device__ __forceinline__ unsigned pack_h2(float hi, float lo) {
    unsigned r;
    asm("cvt.rn.f16x2.f32 %0, %1, %2;" : "=r"(r) : "f"(hi), "f"(lo));
    return r;
}

// packed fp32x2 FMA (Blackwell FFMA2 — only reachable via PTX)
__device__ __forceinline__ unsigned long long pk2(float lo, float hi) {
    unsigned long long r;
    asm("mov.b64 %0, {%1, %2};" : "=l"(r) : "f"(lo), "f"(hi));
    return r;
}
__device__ __forceinline__ void fma2(unsigned long long& d, unsigned long long a,
                                     unsigned long long b, unsigned long long c) {
    asm("fma.rn.f32x2 %0, %1, %2, %3;" : "=l"(d) : "l"(a), "l"(b), "l"(c));
}
__device__ __forceinline__ float2 upk2(unsigned long long v) {
    float2 f;
    asm("mov.b64 {%0, %1}, %2;" : "=f"(f.x), "=f"(f.y) : "l"(v));
    return f;
}

// ---------------- kernel 1: zero scratch -----------------------------------
__global__ void zero_kernel() {
    long i = (long)blockIdx.x * blockDim.x + threadIdx.x;
    long stride = (long)gridDim.x * blockDim.x;
    float* acc = (float*)g_accum;
    for (long j = i; j < (long)NN * HO; j += stride) acc[j] = 0.f;
    for (long j = i; j < (long)NN * HH; j += stride) g_denom[j] = 0.f;
    for (long j = i; j < (long)NN; j += stride) g_deg[j] = 0.f;
    for (long j = i; j < (long)NN * EDIM; j += stride) g_asum[j] = 0.f;
}

// ---------------- kernel 2: degree + attr scatter-sum ----------------------
__global__ void deg_attr_kernel(const int* __restrict__ ei,
                                const float* __restrict__ eattr) {
    int e = blockIdx.x * blockDim.x + threadIdx.x;
    if (e >= EE) return;
    int t = ei[EE + e];
    const float4* a4 = (const float4*)&eattr[(long)e * EDIM];
    float4* dst = &((float4*)g_asum)[(long)t * 4];
#pragma unroll
    for (int q = 0; q < 4; q++) red_add_v4(&dst[q], a4[q]);
    atomicAdd(&g_deg[t], 1.f);
}

// ---------------- kernel 3: x_l / x_r GEMMs with FFMA2, fp16 out -----------
__global__ void gemm_xlr(const float* __restrict__ x,
                         const float* __restrict__ Wl, const float* __restrict__ bl,
                         const float* __restrict__ Wr, const float* __restrict__ br) {
    __shared__ float xs[64][INC];
    int row0 = blockIdx.x * 64;
    int tid = threadIdx.x;

    const float4* x4 = (const float4*)x;
    for (int i = tid; i < 64 * 32; i += 256) {
        int r = i >> 5, c = i & 31;
        float4 v = make_float4(0.f, 0.f, 0.f, 0.f);
        if (row0 + r < NN) v = x4[(long)(row0 + r) * 32 + c];
        ((float4*)xs[r])[c] = v;
    }
    __syncthreads();

    int tx = tid & 31, ty = tid >> 5;
    unsigned long long accL[8][2], accR[8][2];
    unsigned long long z2 = pk2(0.f, 0.f);
#pragma unroll
    for (int r = 0; r < 8; r++) {
        accL[r][0] = z2; accL[r][1] = z2;
        accR[r][0] = z2; accR[r][1] = z2;
    }
    const float4* Wl4 = (const float4*)Wl;
    const float4* Wr4 = (const float4*)Wr;
    for (int k = 0; k < INC; k++) {
        float4 wl = Wl4[k * 32 + tx];
        float4 wr = Wr4[k * 32 + tx];
        unsigned long long wl0 = pk2(wl.x, wl.y), wl1 = pk2(wl.z, wl.w);
        unsigned long long wr0 = pk2(wr.x, wr.y), wr1 = pk2(wr.z, wr.w);
#pragma unroll
        for (int r = 0; r < 8; r++) {
            float xv = xs[ty + r * 8][k];
            unsigned long long xv2 = pk2(xv, xv);
            fma2(accL[r][0], xv2, wl0, accL[r][0]);
            fma2(accL[r][1], xv2, wl1, accL[r][1]);
            fma2(accR[r][0], xv2, wr0, accR[r][0]);
            fma2(accR[r][1], xv2, wr1, accR[r][1]);
        }
    }
    float4 blv = ((const float4*)bl)[tx];
    float4 brv = ((const float4*)br)[tx];
#pragma unroll
    for (int r = 0; r < 8; r++) {
        int row = row0 + ty + r * 8;
        if (row < NN) {
            float2 l0 = upk2(accL[r][0]), l1 = upk2(accL[r][1]);
            float2 r0 = upk2(accR[r][0]), r1 = upk2(accR[r][1]);
            uint2 lo, ro;
            lo.x = pack_h2(l0.y + blv.y, l0.x + blv.x);
            lo.y = pack_h2(l1.y + blv.w, l1.x + blv.z);
            ro.x = pack_h2(r0.y + brv.y, r0.x + brv.x);
            ro.y = pack_h2(r1.y + brv.w, r1.x + brv.z);
            g_xlh[(size_t)row * 32 + tx] = lo;
            g_xrh[(size_t)row * 32 + tx] = ro;
        }
    }
}

// ---------------- kernel 4: edge projection via tensor cores ---------------
// Warp computes 16 rows x 128 cols of E = attr_full @ W_e using 16x
// mma.sync.m16n8k16 (fp16 in, fp32 acc). E stored fp16 in FRAGMENT-PERMUTED
// order: word index = batch*1024 + tile*64 + sel*32 + srclane.
__global__ void __launch_bounds__(256)
egemm_mma_kernel(const float* __restrict__ eattr,
                 const float* __restrict__ We) {
    int lane = threadIdx.x & 31;
    long warpid = (long)blockIdx.x * 8 + (threadIdx.x >> 5);
    if (warpid >= NBATCH) return;
    int grp = lane >> 2, ctg = lane & 3;

    unsigned b0[16], b1[16];
#pragma unroll
    for (int t = 0; t < 16; t++) {
        int col = t * 8 + grp;
        float x0 = __ldg(&We[(2 * ctg) * HO + col]);
        float x1 = __ldg(&We[(2 * ctg + 1) * HO + col]);
        float x2 = __ldg(&We[(2 * ctg + 8) * HO + col]);
        float x3 = __ldg(&We[(2 * ctg + 9) * HO + col]);
        b0[t] = pack_h2(x1, x0);
        b1[t] = pack_h2(x3, x2);
    }

    long base = warpid * 16;
    unsigned a0, a1, a2, a3;
    {
        long row = base + grp;
        const float* p; float inv = 1.f;
        if (row < EE) { p = &eattr[row * EDIM]; }
        else { int n = (int)(row - EE); p = &g_asum[(size_t)n * EDIM];
               inv = 1.f / fmaxf(g_deg[n], 1.f); }
        float2 lo = *(const float2*)(p + 2 * ctg);
        float2 hi = *(const float2*)(p + 2 * ctg + 8);
        a0 = pack_h2(lo.y * inv, lo.x * inv);
        a2 = pack_h2(hi.y * inv, hi.x * inv);
    }
    {
        long row = base + grp + 8;
        const float* p; float inv = 1.f;
        if (row < EE) { p = &eattr[row * EDIM]; }
        else { int n = (int)(row - EE); p = &g_asum[(size_t)n * EDIM];
               inv = 1.f / fmaxf(g_deg[n], 1.f); }
        float2 lo = *(const float2*)(p + 2 * ctg);
        float2 hi = *(const float2*)(p + 2 * ctg + 8);
        a1 = pack_h2(lo.y * inv, lo.x * inv);
        a3 = pack_h2(hi.y * inv, hi.x * inv);
    }

    unsigned* outp = g_eperm + (size_t)warpid * 1024;
    float z = 0.f;
#pragma unroll
    for (int t = 0; t < 16; t++) {
        float d0, d1, d2, d3;
        asm volatile(
            "mma.sync.aligned.m16n8k16.row.col.f32.f16.f16.f32 "
            "{%0,%1,%2,%3}, {%4,%5,%6,%7}, {%8,%9}, {%10,%10,%10,%10};"
            : "=f"(d0), "=f"(d1), "=f"(d2), "=f"(d3)
            : "r"(a0), "r"(a1), "r"(a2), "r"(a3),
              "r"(b0[t]), "r"(b1[t]), "f"(z));
        outp[t * 64 + lane]      = pack_h2(d1, d0);   // rows grp   (sel 0)
        outp[t * 64 + 32 + lane] = pack_h2(d3, d2);   // rows grp+8 (sel 1)
    }
}

// ---------------- kernel 5: LIGHT edge pass (fp16 gathers) ------------------
// One warp per edge; lane owns channel quad. xl/xr gathered fp16 (8B/lane),
// E read from fragment-permuted buffer (8B/lane). exp without max-sub
// (alpha identical, scores bounded). RED in fp32 (required range).
__global__ void __launch_bounds__(256)
edge_light_kernel(const int* __restrict__ ei,
                  const float* __restrict__ att) {
    int lane = threadIdx.x & 31;
    long ew = (long)blockIdx.x * 8 + (threadIdx.x >> 5);
    if (ew >= ENF) return;

    int s, t;
    if (ew < EE) { s = __ldg(&ei[ew]); t = __ldg(&ei[EE + ew]); }
    else         { s = t = (int)(ew - EE); }

    uint2 xlh = __ldg(&g_xlh[(size_t)s * 32 + lane]);
    uint2 xrh = __ldg(&g_xrh[(size_t)t * 32 + lane]);
    float2 xl01 = __half22float2(*(__half2*)&xlh.x);
    float2 xl23 = __half22float2(*(__half2*)&xlh.y);
    float2 xr01 = __half22float2(*(__half2*)&xrh.x);
    float2 xr23 = __half22float2(*(__half2*)&xrh.y);

    // E from fragment-permuted layout
    long batch = ew >> 4;
    int g16 = (int)(ew & 15);
    int sel = g16 >> 3, gval = g16 & 7;
    int tile = lane >> 1, q = lane & 1;
    uint2 ev = __ldg((const uint2*)(g_eperm + (size_t)batch * 1024 +
                                   tile * 64 + sel * 32 + 4 * gval + 2 * q));
    float2 e01 = __half22float2(*(__half2*)&ev.x);
    float2 e23 = __half22float2(*(__half2*)&ev.y);

    float4 av = __ldg(&((const float4*)att)[lane]);

    float m0 = lrelu(xl01.x + xr01.x + e01.x);
    float m1 = lrelu(xl01.y + xr01.y + e01.y);
    float m2 = lrelu(xl23.x + xr23.x + e23.x);
    float m3 = lrelu(xl23.y + xr23.y + e23.y);
    float p = m0 * av.x + m1 * av.y + m2 * av.z + m3 * av.w;
    p += __shfl_xor_sync(0xffffffffu, p, 4);
    p += __shfl_xor_sync(0xffffffffu, p, 2);
    p += __shfl_xor_sync(0xffffffffu, p, 1);

    float ex = __expf(p);

    if ((lane & 7) == 0)
        atomicAdd(&g_denom[(size_t)t * HH + (lane >> 3)], ex);

    red_add_v4(&g_accum[(long)t * 32 + lane],
               make_float4(ex * xl01.x, ex * xl01.y, ex * xl23.x, ex * xl23.y));
}

// ---------------- kernel 6: finalize (head mean + bias + LeakyReLU) --------
__global__ void finalize_kernel(const float* __restrict__ bias,
                                float* __restrict__ out) {
    int idx = blockIdx.x * blockDim.x + threadIdx.x;
    if (idx >= NN * OUTC) return;
    int n = idx >> 5, c = idx & 31;
    const float* acc = (const float*)g_accum;
    float sum = 0.f;
#pragma unroll
    for (int hh = 0; hh < HH; hh++)
        sum += acc[(size_t)n * HO + hh * OUTC + c] / g_denom[(size_t)n * HH + hh];
    float o = sum * 0.25f + bias[c];
    out[idx] = lrelu(o);
}

// ---------------- launch ---------------------------------------------------
extern "C" void kernel_launch(void* const* d_in, const int* in_sizes, int n_in,
                              void* d_out, int out_size) {
    const float* x     = (const float*)d_in[0];
    const int*   ei    = (const int*)  d_in[1];
    const float* eattr = (const float*)d_in[2];
    const float* Wl    = (const float*)d_in[3];
    const float* bl    = (const float*)d_in[4];
    const float* Wr    = (const float*)d_in[5];
    const float* br    = (const float*)d_in[6];
    const float* We    = (const float*)d_in[7];
    const float* att   = (const float*)d_in[8];
    const float* bias  = (const float*)d_in[9];
    float* out = (float*)d_out;

    zero_kernel<<<2048, 256>>>();
    deg_attr_kernel<<<(EE + 255) / 256, 256>>>(ei, eattr);
    gemm_xlr<<<(NN + 63) / 64, 256>>>(x, Wl, bl, Wr, br);
    egemm_mma_kernel<<<(NBATCH + 7) / 8, 256>>>(eattr, We);
    edge_light_kernel<<<(ENF + 7) / 8, 256>>>(ei, att);
    finalize_kernel<<<(NN * OUTC + 255) / 256, 256>>>(bias, out);
}

// round 10
// speedup vs baseline: 1.4336x; 1.2825x over previous
#include <cuda_runtime.h>
#include <cuda_fp16.h>

#define NN   50000
#define EE   800000
#define INC  128
#define OUTC 32
#define HH   4
#define EDIM 16
#define HO   128          // H*OUT
#define ENF  (EE + NN)    // edges + self loops = 850000 (divisible by 16)
#define NBATCH (ENF / 16) // 53125 mma warp batches
#define SLOPE 0.2f

// ---------------- scratch (device globals; no allocation allowed) ----------
__device__ uint2    g_xlh[(size_t)NN * 32];      // x@W_l+b_l fp16 (12.8 MB)
__device__ uint2    g_xrh[(size_t)NN * 32];      // x@W_r+b_r fp16 (12.8 MB)
__device__ float    g_deg[NN];                   // in-degree
__device__ float    g_asum[(size_t)NN * EDIM];   // scatter-sum of edge attrs
__device__ float    g_denom[(size_t)NN * HH];    // softmax denominators
__device__ float4   g_accum[(size_t)NN * OUTC];  // sum exp(s)*x_l[src] (25.6 MB)

// ---------------- helpers --------------------------------------------------
__device__ __forceinline__ float lrelu(float v) { return v > 0.f ? v : SLOPE * v; }

__device__ __forceinline__ void red_add_v4(float4* addr, float4 v) {
    asm volatile("red.global.add.v4.f32 [%0], {%1,%2,%3,%4};"
                 :: "l"(addr), "f"(v.x), "f"(v.y), "f"(v.z), "f"(v.w)
                 : "memory");
}

// pack two f32 into f16x2: lo -> bits[15:0], hi -> bits[31:16]
__device__ __forceinline__ unsigned pack_h2(float hi, float lo) {
    unsigned r;
    asm("cvt.rn.f16x2.f32 %0, %1, %2;" : "=r"(r) : "f"(hi), "f"(lo));
    return r;
}

// packed fp32x2 FMA (Blackwell FFMA2 — only reachable via PTX)
__device__ __forceinline__ unsigned long long pk2(float lo, float hi) {
    unsigned long long r;
    asm("mov.b64 %0, {%1, %2};" : "=l"(r) : "f"(lo), "f"(hi));
    return r;
}
__device__ __forceinline__ void fma2(unsigned long long& d, unsigned long long a,
                                     unsigned long long b, unsigned long long c) {
    asm("fma.rn.f32x2 %0, %1, %2, %3;" : "=l"(d) : "l"(a), "l"(b), "l"(c));
}
__device__ __forceinline__ float2 upk2(unsigned long long v) {
    float2 f;
    asm("mov.b64 {%0, %1}, %2;" : "=f"(f.x), "=f"(f.y) : "l"(v));
    return f;
}

// ---------------- kernel 1: zero scratch -----------------------------------
__global__ void zero_kernel() {
    long i = (long)blockIdx.x * blockDim.x + threadIdx.x;
    long stride = (long)gridDim.x * blockDim.x;
    float* acc = (float*)g_accum;
    for (long j = i; j < (long)NN * HO; j += stride) acc[j] = 0.f;
    for (long j = i; j < (long)NN * HH; j += stride) g_denom[j] = 0.f;
    for (long j = i; j < (long)NN; j += stride) g_deg[j] = 0.f;
    for (long j = i; j < (long)NN * EDIM; j += stride) g_asum[j] = 0.f;
}

// ---------------- kernel 2: degree + attr scatter-sum ----------------------
__global__ void deg_attr_kernel(const int* __restrict__ ei,
                                const float* __restrict__ eattr) {
    int e = blockIdx.x * blockDim.x + threadIdx.x;
    if (e >= EE) return;
    int t = ei[EE + e];
    const float4* a4 = (const float4*)&eattr[(long)e * EDIM];
    float4* dst = &((float4*)g_asum)[(long)t * 4];
#pragma unroll
    for (int q = 0; q < 4; q++) red_add_v4(&dst[q], a4[q]);
    atomicAdd(&g_deg[t], 1.f);
}

// ---------------- kernel 3: x_l / x_r GEMMs with FFMA2, fp16 out -----------
__global__ void gemm_xlr(const float* __restrict__ x,
                         const float* __restrict__ Wl, const float* __restrict__ bl,
                         const float* __restrict__ Wr, const float* __restrict__ br) {
    __shared__ float xs[64][INC];
    int row0 = blockIdx.x * 64;
    int tid = threadIdx.x;

    const float4* x4 = (const float4*)x;
    for (int i = tid; i < 64 * 32; i += 256) {
        int r = i >> 5, c = i & 31;
        float4 v = make_float4(0.f, 0.f, 0.f, 0.f);
        if (row0 + r < NN) v = x4[(long)(row0 + r) * 32 + c];
        ((float4*)xs[r])[c] = v;
    }
    __syncthreads();

    int tx = tid & 31, ty = tid >> 5;
    unsigned long long accL[8][2], accR[8][2];
    unsigned long long z2 = pk2(0.f, 0.f);
#pragma unroll
    for (int r = 0; r < 8; r++) {
        accL[r][0] = z2; accL[r][1] = z2;
        accR[r][0] = z2; accR[r][1] = z2;
    }
    const float4* Wl4 = (const float4*)Wl;
    const float4* Wr4 = (const float4*)Wr;
    for (int k = 0; k < INC; k++) {
        float4 wl = Wl4[k * 32 + tx];
        float4 wr = Wr4[k * 32 + tx];
        unsigned long long wl0 = pk2(wl.x, wl.y), wl1 = pk2(wl.z, wl.w);
        unsigned long long wr0 = pk2(wr.x, wr.y), wr1 = pk2(wr.z, wr.w);
#pragma unroll
        for (int r = 0; r < 8; r++) {
            float xv = xs[ty + r * 8][k];
            unsigned long long xv2 = pk2(xv, xv);
            fma2(accL[r][0], xv2, wl0, accL[r][0]);
            fma2(accL[r][1], xv2, wl1, accL[r][1]);
            fma2(accR[r][0], xv2, wr0, accR[r][0]);
            fma2(accR[r][1], xv2, wr1, accR[r][1]);
        }
    }
    float4 blv = ((const float4*)bl)[tx];
    float4 brv = ((const float4*)br)[tx];
#pragma unroll
    for (int r = 0; r < 8; r++) {
        int row = row0 + ty + r * 8;
        if (row < NN) {
            float2 l0 = upk2(accL[r][0]), l1 = upk2(accL[r][1]);
            float2 r0 = upk2(accR[r][0]), r1 = upk2(accR[r][1]);
            uint2 lo, ro;
            lo.x = pack_h2(l0.y + blv.y, l0.x + blv.x);
            lo.y = pack_h2(l1.y + blv.w, l1.x + blv.z);
            ro.x = pack_h2(r0.y + brv.y, r0.x + brv.x);
            ro.y = pack_h2(r1.y + brv.w, r1.x + brv.z);
            g_xlh[(size_t)row * 32 + tx] = lo;
            g_xrh[(size_t)row * 32 + tx] = ro;
        }
    }
}

// ---------------- kernel 4: FUSED mma edge projection + edge pass ----------
// Warp grid-strides over 16-edge batches. Per batch: E(16x128) = attr @ W_e
// via 16x mma.m16n8k16 (B-fragments of W_e cached in regs ONCE per warp),
// fragments parked in padded smem (stride 68 words: conflict-free STS,
// 2-way LDS.64 = structural floor), then the 16 edges are processed:
// gather xl/xr (fp16), score, exp (no max-sub: alpha identical, bounded),
// scatter denom + exp*xl via RED.v4.
#define SMS 68   // smem row stride in words
__global__ void __launch_bounds__(256)
edge_mma_fused(const int* __restrict__ ei,
               const float* __restrict__ eattr,
               const float* __restrict__ We,
               const float* __restrict__ att) {
    __shared__ unsigned es[8][16 * SMS];
    int lane = threadIdx.x & 31;
    int w = threadIdx.x >> 5;
    unsigned* sm = es[w];
    int grp = lane >> 2, ctg = lane & 3;

    // B fragments for all 16 n-tiles (once per warp)
    unsigned b0[16], b1[16];
#pragma unroll
    for (int t = 0; t < 16; t++) {
        int col = t * 8 + grp;
        float x0 = __ldg(&We[(2 * ctg) * HO + col]);
        float x1 = __ldg(&We[(2 * ctg + 1) * HO + col]);
        float x2 = __ldg(&We[(2 * ctg + 8) * HO + col]);
        float x3 = __ldg(&We[(2 * ctg + 9) * HO + col]);
        b0[t] = pack_h2(x1, x0);
        b1[t] = pack_h2(x3, x2);
    }
    float4 av = __ldg(&((const float4*)att)[lane]);

    // consumer smem word offset for this lane's channel quad
    int pw = (lane >> 1) * 4 + 2 * (lane & 1);

    long warp0 = (long)blockIdx.x * 8 + w;
    long nwarp = (long)gridDim.x * 8;

    for (long batch = warp0; batch < NBATCH; batch += nwarp) {
        long base = batch * 16;

        // ---- A fragments: rows base+grp (a0,a2), base+grp+8 (a1,a3) ----
        unsigned a0, a1, a2, a3;
        {
            long row = base + grp;
            const float* p; float inv = 1.f;
            if (row < EE) { p = &eattr[row * EDIM]; }
            else { int n = (int)(row - EE); p = &g_asum[(size_t)n * EDIM];
                   inv = 1.f / fmaxf(g_deg[n], 1.f); }
            float2 lo = *(const float2*)(p + 2 * ctg);
            float2 hi = *(const float2*)(p + 2 * ctg + 8);
            a0 = pack_h2(lo.y * inv, lo.x * inv);
            a2 = pack_h2(hi.y * inv, hi.x * inv);
        }
        {
            long row = base + grp + 8;
            const float* p; float inv = 1.f;
            if (row < EE) { p = &eattr[row * EDIM]; }
            else { int n = (int)(row - EE); p = &g_asum[(size_t)n * EDIM];
                   inv = 1.f / fmaxf(g_deg[n], 1.f); }
            float2 lo = *(const float2*)(p + 2 * ctg);
            float2 hi = *(const float2*)(p + 2 * ctg + 8);
            a1 = pack_h2(lo.y * inv, lo.x * inv);
            a3 = pack_h2(hi.y * inv, hi.x * inv);
        }

        // ---- 16 mma -> smem fragments ----
        float z = 0.f;
#pragma unroll
        for (int t = 0; t < 16; t++) {
            float d0, d1, d2, d3;
            asm volatile(
                "mma.sync.aligned.m16n8k16.row.col.f32.f16.f16.f32 "
                "{%0,%1,%2,%3}, {%4,%5,%6,%7}, {%8,%9}, {%10,%10,%10,%10};"
                : "=f"(d0), "=f"(d1), "=f"(d2), "=f"(d3)
                : "r"(a0), "r"(a1), "r"(a2), "r"(a3),
                  "r"(b0[t]), "r"(b1[t]), "f"(z));
            sm[grp * SMS + t * 4 + ctg]       = pack_h2(d1, d0);
            sm[(grp + 8) * SMS + t * 4 + ctg] = pack_h2(d3, d2);
        }
        __syncwarp();

        // ---- process the 16 edges of this batch ----
#pragma unroll 4
        for (int g16 = 0; g16 < 16; g16++) {
            long ew = base + g16;
            int s, t;
            if (ew < EE) { s = __ldg(&ei[ew]); t = __ldg(&ei[EE + ew]); }
            else         { s = t = (int)(ew - EE); }

            uint2 xlh = __ldg(&g_xlh[(size_t)s * 32 + lane]);
            uint2 xrh = __ldg(&g_xrh[(size_t)t * 32 + lane]);
            float2 xl01 = __half22float2(*(__half2*)&xlh.x);
            float2 xl23 = __half22float2(*(__half2*)&xlh.y);
            float2 xr01 = __half22float2(*(__half2*)&xrh.x);
            float2 xr23 = __half22float2(*(__half2*)&xrh.y);

            uint2 ev = *(const uint2*)&sm[g16 * SMS + pw];
            float2 e01 = __half22float2(*(__half2*)&ev.x);
            float2 e23 = __half22float2(*(__half2*)&ev.y);

            float m0 = lrelu(xl01.x + xr01.x + e01.x);
            float m1 = lrelu(xl01.y + xr01.y + e01.y);
            float m2 = lrelu(xl23.x + xr23.x + e23.x);
            float m3 = lrelu(xl23.y + xr23.y + e23.y);
            float p = m0 * av.x + m1 * av.y + m2 * av.z + m3 * av.w;
            p += __shfl_xor_sync(0xffffffffu, p, 4);
            p += __shfl_xor_sync(0xffffffffu, p, 2);
            p += __shfl_xor_sync(0xffffffffu, p, 1);

            float ex = __expf(p);

            if ((lane & 7) == 0)
                atomicAdd(&g_denom[(size_t)t * HH + (lane >> 3)], ex);

            red_add_v4(&g_accum[(long)t * 32 + lane],
                       make_float4(ex * xl01.x, ex * xl01.y,
                                   ex * xl23.x, ex * xl23.y));
        }
        __syncwarp();   // protect smem before next batch overwrites
    }
}

// ---------------- kernel 5: finalize (head mean + bias + LeakyReLU) --------
__global__ void finalize_kernel(const float* __restrict__ bias,
                                float* __restrict__ out) {
    int idx = blockIdx.x * blockDim.x + threadIdx.x;
    if (idx >= NN * OUTC) return;
    int n = idx >> 5, c = idx & 31;
    const float* acc = (const float*)g_accum;
    float sum = 0.f;
#pragma unroll
    for (int hh = 0; hh < HH; hh++)
        sum += acc[(size_t)n * HO + hh * OUTC + c] / g_denom[(size_t)n * HH + hh];
    float o = sum * 0.25f + bias[c];
    out[idx] = lrelu(o);
}

// ---------------- launch ---------------------------------------------------
extern "C" void kernel_launch(void* const* d_in, const int* in_sizes, int n_in,
                              void* d_out, int out_size) {
    const float* x     = (const float*)d_in[0];
    const int*   ei    = (const int*)  d_in[1];
    const float* eattr = (const float*)d_in[2];
    const float* Wl    = (const float*)d_in[3];
    const float* bl    = (const float*)d_in[4];
    const float* Wr    = (const float*)d_in[5];
    const float* br    = (const float*)d_in[6];
    const float* We    = (const float*)d_in[7];
    const float* att   = (const float*)d_in[8];
    const float* bias  = (const float*)d_in[9];
    float* out = (float*)d_out;

    zero_kernel<<<2048, 256>>>();
    deg_attr_kernel<<<(EE + 255) / 256, 256>>>(ei, eattr);
    gemm_xlr<<<(NN + 63) / 64, 256>>>(x, Wl, bl, Wr, br);
    // ~6656 warps, each handles ~8 batches of 16 edges
    edge_mma_fused<<<832, 256>>>(ei, eattr, We, att);
    finalize_kernel<<<(NN * OUTC + 255) / 256, 256>>>(bias, out);
}

// round 11
// speedup vs baseline: 1.4339x; 1.0002x over previous
#include <cuda_runtime.h>
#include <cuda_fp16.h>

#define NN   50000
#define EE   800000
#define INC  128
#define OUTC 32
#define HH   4
#define EDIM 16
#define HO   128          // H*OUT
#define ENF  (EE + NN)    // edges + self loops = 850000 (divisible by 16)
#define NBATCH (ENF / 16) // 53125 mma warp batches
#define SLOPE 0.2f

// ---------------- scratch (device globals; no allocation allowed) ----------
__device__ uint2    g_xlh[(size_t)NN * 32];      // x@W_l+b_l fp16 (12.8 MB)
__device__ uint2    g_xrh[(size_t)NN * 32];      // x@W_r+b_r fp16 (12.8 MB)
__device__ float    g_deg[NN];                   // in-degree
__device__ float    g_asum[(size_t)NN * EDIM];   // scatter-sum of edge attrs
__device__ float    g_denom[(size_t)NN * HH];    // softmax denominators
__device__ float4   g_accum[(size_t)NN * OUTC];  // sum exp(s)*x_l[src] (25.6 MB)

// ---------------- helpers --------------------------------------------------
__device__ __forceinline__ float lrelu(float v) { return v > 0.f ? v : SLOPE * v; }

__device__ __forceinline__ void red_add_v4(float4* addr, float4 v) {
    asm volatile("red.global.add.v4.f32 [%0], {%1,%2,%3,%4};"
                 :: "l"(addr), "f"(v.x), "f"(v.y), "f"(v.z), "f"(v.w)
                 : "memory");
}

// pack two f32 into f16x2: lo -> bits[15:0], hi -> bits[31:16]
__device__ __forceinline__ unsigned pack_h2(float hi, float lo) {
    unsigned r;
    asm("cvt.rn.f16x2.f32 %0, %1, %2;" : "=r"(r) : "f"(hi), "f"(lo));
    return r;
}

// packed fp32x2 FMA (Blackwell FFMA2 — only reachable via PTX)
__device__ __forceinline__ unsigned long long pk2(float lo, float hi) {
    unsigned long long r;
    asm("mov.b64 %0, {%1, %2};" : "=l"(r) : "f"(lo), "f"(hi));
    return r;
}
__device__ __forceinline__ void fma2(unsigned long long& d, unsigned long long a,
                                     unsigned long long b, unsigned long long c) {
    asm("fma.rn.f32x2 %0, %1, %2, %3;" : "=l"(d) : "l"(a), "l"(b), "l"(c));
}
__device__ __forceinline__ float2 upk2(unsigned long long v) {
    float2 f;
    asm("mov.b64 {%0, %1}, %2;" : "=f"(f.x), "=f"(f.y) : "l"(v));
    return f;
}

// ---------------- kernel 1: zero scratch -----------------------------------
__global__ void zero_kernel() {
    long i = (long)blockIdx.x * blockDim.x + threadIdx.x;
    long stride = (long)gridDim.x * blockDim.x;
    float* acc = (float*)g_accum;
    for (long j = i; j < (long)NN * HO; j += stride) acc[j] = 0.f;
    for (long j = i; j < (long)NN * HH; j += stride) g_denom[j] = 0.f;
    for (long j = i; j < (long)NN; j += stride) g_deg[j] = 0.f;
    for (long j = i; j < (long)NN * EDIM; j += stride) g_asum[j] = 0.f;
}

// ---------------- kernel 2: degree + attr scatter-sum ----------------------
__global__ void deg_attr_kernel(const int* __restrict__ ei,
                                const float* __restrict__ eattr) {
    int e = blockIdx.x * blockDim.x + threadIdx.x;
    if (e >= EE) return;
    int t = ei[EE + e];
    const float4* a4 = (const float4*)&eattr[(long)e * EDIM];
    float4* dst = &((float4*)g_asum)[(long)t * 4];
#pragma unroll
    for (int q = 0; q < 4; q++) red_add_v4(&dst[q], a4[q]);
    atomicAdd(&g_deg[t], 1.f);
}

// ---------------- kernel 3: x_l / x_r GEMMs with FFMA2, fp16 out -----------
__global__ void gemm_xlr(const float* __restrict__ x,
                         const float* __restrict__ Wl, const float* __restrict__ bl,
                         const float* __restrict__ Wr, const float* __restrict__ br) {
    __shared__ float xs[64][INC];
    int row0 = blockIdx.x * 64;
    int tid = threadIdx.x;

    const float4* x4 = (const float4*)x;
    for (int i = tid; i < 64 * 32; i += 256) {
        int r = i >> 5, c = i & 31;
        float4 v = make_float4(0.f, 0.f, 0.f, 0.f);
        if (row0 + r < NN) v = x4[(long)(row0 + r) * 32 + c];
        ((float4*)xs[r])[c] = v;
    }
    __syncthreads();

    int tx = tid & 31, ty = tid >> 5;
    unsigned long long accL[8][2], accR[8][2];
    unsigned long long z2 = pk2(0.f, 0.f);
#pragma unroll
    for (int r = 0; r < 8; r++) {
        accL[r][0] = z2; accL[r][1] = z2;
        accR[r][0] = z2; accR[r][1] = z2;
    }
    const float4* Wl4 = (const float4*)Wl;
    const float4* Wr4 = (const float4*)Wr;
    for (int k = 0; k < INC; k++) {
        float4 wl = Wl4[k * 32 + tx];
        float4 wr = Wr4[k * 32 + tx];
        unsigned long long wl0 = pk2(wl.x, wl.y), wl1 = pk2(wl.z, wl.w);
        unsigned long long wr0 = pk2(wr.x, wr.y), wr1 = pk2(wr.z, wr.w);
#pragma unroll
        for (int r = 0; r < 8; r++) {
            float xv = xs[ty + r * 8][k];
            unsigned long long xv2 = pk2(xv, xv);
            fma2(accL[r][0], xv2, wl0, accL[r][0]);
            fma2(accL[r][1], xv2, wl1, accL[r][1]);
            fma2(accR[r][0], xv2, wr0, accR[r][0]);
            fma2(accR[r][1], xv2, wr1, accR[r][1]);
        }
    }
    float4 blv = ((const float4*)bl)[tx];
    float4 brv = ((const float4*)br)[tx];
#pragma unroll
    for (int r = 0; r < 8; r++) {
        int row = row0 + ty + r * 8;
        if (row < NN) {
            float2 l0 = upk2(accL[r][0]), l1 = upk2(accL[r][1]);
            float2 r0 = upk2(accR[r][0]), r1 = upk2(accR[r][1]);
            uint2 lo, ro;
            lo.x = pack_h2(l0.y + blv.y, l0.x + blv.x);
            lo.y = pack_h2(l1.y + blv.w, l1.x + blv.z);
            ro.x = pack_h2(r0.y + brv.y, r0.x + brv.x);
            ro.y = pack_h2(r1.y + brv.w, r1.x + brv.z);
            g_xlh[(size_t)row * 32 + tx] = lo;
            g_xrh[(size_t)row * 32 + tx] = ro;
        }
    }
}

// ---------------- kernel 4: FUSED mma edge projection + edge pass ----------
// Warp grid-strides over 16-edge batches. Per batch: E(16x128) = attr @ W_e
// via 16x mma.m16n8k16 (B-fragments of W_e cached in regs ONCE per warp),
// fragments parked in padded smem (stride 68 words: conflict-free STS,
// 2-way LDS.64 = structural floor), then the 16 edges are processed:
// gather xl/xr (fp16), score, exp (no max-sub: alpha identical, bounded),
// scatter denom + exp*xl via RED.v4.
#define SMS 68   // smem row stride in words
__global__ void __launch_bounds__(256)
edge_mma_fused(const int* __restrict__ ei,
               const float* __restrict__ eattr,
               const float* __restrict__ We,
               const float* __restrict__ att) {
    __shared__ unsigned es[8][16 * SMS];
    int lane = threadIdx.x & 31;
    int w = threadIdx.x >> 5;
    unsigned* sm = es[w];
    int grp = lane >> 2, ctg = lane & 3;

    // B fragments for all 16 n-tiles (once per warp)
    unsigned b0[16], b1[16];
#pragma unroll
    for (int t = 0; t < 16; t++) {
        int col = t * 8 + grp;
        float x0 = __ldg(&We[(2 * ctg) * HO + col]);
        float x1 = __ldg(&We[(2 * ctg + 1) * HO + col]);
        float x2 = __ldg(&We[(2 * ctg + 8) * HO + col]);
        float x3 = __ldg(&We[(2 * ctg + 9) * HO + col]);
        b0[t] = pack_h2(x1, x0);
        b1[t] = pack_h2(x3, x2);
    }
    float4 av = __ldg(&((const float4*)att)[lane]);

    // consumer smem word offset for this lane's channel quad
    int pw = (lane >> 1) * 4 + 2 * (lane & 1);

    long warp0 = (long)blockIdx.x * 8 + w;
    long nwarp = (long)gridDim.x * 8;

    for (long batch = warp0; batch < NBATCH; batch += nwarp) {
        long base = batch * 16;

        // ---- A fragments: rows base+grp (a0,a2), base+grp+8 (a1,a3) ----
        unsigned a0, a1, a2, a3;
        {
            long row = base + grp;
            const float* p; float inv = 1.f;
            if (row < EE) { p = &eattr[row * EDIM]; }
            else { int n = (int)(row - EE); p = &g_asum[(size_t)n * EDIM];
                   inv = 1.f / fmaxf(g_deg[n], 1.f); }
            float2 lo = *(const float2*)(p + 2 * ctg);
            float2 hi = *(const float2*)(p + 2 * ctg + 8);
            a0 = pack_h2(lo.y * inv, lo.x * inv);
            a2 = pack_h2(hi.y * inv, hi.x * inv);
        }
        {
            long row = base + grp + 8;
            const float* p; float inv = 1.f;
            if (row < EE) { p = &eattr[row * EDIM]; }
            else { int n = (int)(row - EE); p = &g_asum[(size_t)n * EDIM];
                   inv = 1.f / fmaxf(g_deg[n], 1.f); }
            float2 lo = *(const float2*)(p + 2 * ctg);
            float2 hi = *(const float2*)(p + 2 * ctg + 8);
            a1 = pack_h2(lo.y * inv, lo.x * inv);
            a3 = pack_h2(hi.y * inv, hi.x * inv);
        }

        // ---- 16 mma -> smem fragments ----
        float z = 0.f;
#pragma unroll
        for (int t = 0; t < 16; t++) {
            float d0, d1, d2, d3;
            asm volatile(
                "mma.sync.aligned.m16n8k16.row.col.f32.f16.f16.f32 "
                "{%0,%1,%2,%3}, {%4,%5,%6,%7}, {%8,%9}, {%10,%10,%10,%10};"
                : "=f"(d0), "=f"(d1), "=f"(d2), "=f"(d3)
                : "r"(a0), "r"(a1), "r"(a2), "r"(a3),
                  "r"(b0[t]), "r"(b1[t]), "f"(z));
            sm[grp * SMS + t * 4 + ctg]       = pack_h2(d1, d0);
            sm[(grp + 8) * SMS + t * 4 + ctg] = pack_h2(d3, d2);
        }
        __syncwarp();

        // ---- process the 16 edges of this batch ----
#pragma unroll 4
        for (int g16 = 0; g16 < 16; g16++) {
            long ew = base + g16;
            int s, t;
            if (ew < EE) { s = __ldg(&ei[ew]); t = __ldg(&ei[EE + ew]); }
            else         { s = t = (int)(ew - EE); }

            uint2 xlh = __ldg(&g_xlh[(size_t)s * 32 + lane]);
            uint2 xrh = __ldg(&g_xrh[(size_t)t * 32 + lane]);
            float2 xl01 = __half22float2(*(__half2*)&xlh.x);
            float2 xl23 = __half22float2(*(__half2*)&xlh.y);
            float2 xr01 = __half22float2(*(__half2*)&xrh.x);
            float2 xr23 = __half22float2(*(__half2*)&xrh.y);

            uint2 ev = *(const uint2*)&sm[g16 * SMS + pw];
            float2 e01 = __half22float2(*(__half2*)&ev.x);
            float2 e23 = __half22float2(*(__half2*)&ev.y);

            float m0 = lrelu(xl01.x + xr01.x + e01.x);
            float m1 = lrelu(xl01.y + xr01.y + e01.y);
            float m2 = lrelu(xl23.x + xr23.x + e23.x);
            float m3 = lrelu(xl23.y + xr23.y + e23.y);
            float p = m0 * av.x + m1 * av.y + m2 * av.z + m3 * av.w;
            p += __shfl_xor_sync(0xffffffffu, p, 4);
            p += __shfl_xor_sync(0xffffffffu, p, 2);
            p += __shfl_xor_sync(0xffffffffu, p, 1);

            float ex = __expf(p);

            if ((lane & 7) == 0)
                atomicAdd(&g_denom[(size_t)t * HH + (lane >> 3)], ex);

            red_add_v4(&g_accum[(long)t * 32 + lane],
                       make_float4(ex * xl01.x, ex * xl01.y,
                                   ex * xl23.x, ex * xl23.y));
        }
        __syncwarp();   // protect smem before next batch overwrites
    }
}

// ---------------- kernel 5: finalize (head mean + bias + LeakyReLU) --------
__global__ void finalize_kernel(const float* __restrict__ bias,
                                float* __restrict__ out) {
    int idx = blockIdx.x * blockDim.x + threadIdx.x;
    if (idx >= NN * OUTC) return;
    int n = idx >> 5, c = idx & 31;
    const float* acc = (const float*)g_accum;
    float sum = 0.f;
#pragma unroll
    for (int hh = 0; hh < HH; hh++)
        sum += acc[(size_t)n * HO + hh * OUTC + c] / g_denom[(size_t)n * HH + hh];
    float o = sum * 0.25f + bias[c];
    out[idx] = lrelu(o);
}

// ---------------- launch ---------------------------------------------------
extern "C" void kernel_launch(void* const* d_in, const int* in_sizes, int n_in,
                              void* d_out, int out_size) {
    const float* x     = (const float*)d_in[0];
    const int*   ei    = (const int*)  d_in[1];
    const float* eattr = (const float*)d_in[2];
    const float* Wl    = (const float*)d_in[3];
    const float* bl    = (const float*)d_in[4];
    const float* Wr    = (const float*)d_in[5];
    const float* br    = (const float*)d_in[6];
    const float* We    = (const float*)d_in[7];
    const float* att   = (const float*)d_in[8];
    const float* bias  = (const float*)d_in[9];
    float* out = (float*)d_out;

    zero_kernel<<<2048, 256>>>();
    deg_attr_kernel<<<(EE + 255) / 256, 256>>>(ei, eattr);
    gemm_xlr<<<(NN + 63) / 64, 256>>>(x, Wl, bl, Wr, br);
    // ~6656 warps, each handles ~8 batches of 16 edges
    edge_mma_fused<<<832, 256>>>(ei, eattr, We, att);
    finalize_kernel<<<(NN * OUTC + 255) / 256, 256>>>(bias, out);
}

// round 12
// speedup vs baseline: 1.5671x; 1.0929x over previous
#include <cuda_runtime.h>
#include <cuda_fp16.h>

#define NN   50000
#define EE   800000
#define INC  128
#define OUTC 32
#define HH   4
#define EDIM 16
#define HO   128          // H*OUT
#define ENF  (EE + NN)    // edges + self loops = 850000 (divisible by 16)
#define NBATCH (ENF / 16) // 53125 mma warp batches
#define SLOPE 0.2f

// fat-kernel block partition
#define GEMM_NB 782       // ceil(NN/64)
#define DEG_NB  3125      // ceil(EE/256)
#define ZERO_NB 512
#define FAT_NB  (GEMM_NB + DEG_NB + ZERO_NB)

// ---------------- scratch (device globals; no allocation allowed) ----------
__device__ uint2    g_xlh[(size_t)NN * 32];      // x@W_l+b_l fp16 (12.8 MB)
__device__ uint2    g_xrh[(size_t)NN * 32];      // x@W_r+b_r fp16 (12.8 MB)
__device__ float    g_deg[NN];                   // in-degree
__device__ float    g_asum[(size_t)NN * EDIM];   // scatter-sum of edge attrs
__device__ float    g_denom[(size_t)NN * HH];    // softmax denominators
__device__ float4   g_accum[(size_t)NN * OUTC];  // sum exp(s)*x_l[src] (25.6 MB)

// ---------------- helpers --------------------------------------------------
__device__ __forceinline__ float lrelu(float v) { return fmaxf(v, SLOPE * v); }

__device__ __forceinline__ void red_add_v4(float4* addr, float4 v) {
    asm volatile("red.global.add.v4.f32 [%0], {%1,%2,%3,%4};"
                 :: "l"(addr), "f"(v.x), "f"(v.y), "f"(v.z), "f"(v.w)
                 : "memory");
}

// pack two f32 into f16x2: lo -> bits[15:0], hi -> bits[31:16]
__device__ __forceinline__ unsigned pack_h2(float hi, float lo) {
    unsigned r;
    asm("cvt.rn.f16x2.f32 %0, %1, %2;" : "=r"(r) : "f"(hi), "f"(lo));
    return r;
}

// packed fp32x2 FMA (Blackwell FFMA2 — only reachable via PTX)
__device__ __forceinline__ unsigned long long pk2(float lo, float hi) {
    unsigned long long r;
    asm("mov.b64 %0, {%1, %2};" : "=l"(r) : "f"(lo), "f"(hi));
    return r;
}
__device__ __forceinline__ void fma2(unsigned long long& d, unsigned long long a,
                                     unsigned long long b, unsigned long long c) {
    asm("fma.rn.f32x2 %0, %1, %2, %3;" : "=l"(d) : "l"(a), "l"(b), "l"(c));
}
__device__ __forceinline__ float2 upk2(unsigned long long v) {
    float2 f;
    asm("mov.b64 {%0, %1}, %2;" : "=f"(f.x), "=f"(f.y) : "l"(v));
    return f;
}

// ---------------- kernel 1: FAT prologue ------------------------------------
// blocks [0, GEMM_NB): x@W_l / x@W_r GEMMs (FFMA2), fp16 out
// blocks [GEMM_NB, GEMM_NB+DEG_NB): degree + attr scatter-sum
// blocks [GEMM_NB+DEG_NB, FAT_NB): zero accum + denom
// The three parts are independent (asum/deg pre-zeroed by memset nodes) and
// bound by different pipes (FMA / L2-atomics / DRAM) -> they overlap.
__global__ void __launch_bounds__(256)
fat_prologue(const float* __restrict__ x,
             const float* __restrict__ Wl, const float* __restrict__ bl,
             const float* __restrict__ Wr, const float* __restrict__ br,
             const int* __restrict__ ei,
             const float* __restrict__ eattr) {
    __shared__ float xs[64][INC];
    int b = blockIdx.x;
    int tid = threadIdx.x;

    if (b < GEMM_NB) {
        // ---------------- GEMM part ----------------
        int row0 = b * 64;
        const float4* x4 = (const float4*)x;
        for (int i = tid; i < 64 * 32; i += 256) {
            int r = i >> 5, c = i & 31;
            float4 v = make_float4(0.f, 0.f, 0.f, 0.f);
            if (row0 + r < NN) v = x4[(long)(row0 + r) * 32 + c];
            ((float4*)xs[r])[c] = v;
        }
        __syncthreads();

        int tx = tid & 31, ty = tid >> 5;
        unsigned long long accL[8][2], accR[8][2];
        unsigned long long z2 = pk2(0.f, 0.f);
#pragma unroll
        for (int r = 0; r < 8; r++) {
            accL[r][0] = z2; accL[r][1] = z2;
            accR[r][0] = z2; accR[r][1] = z2;
        }
        const float4* Wl4 = (const float4*)Wl;
        const float4* Wr4 = (const float4*)Wr;
        for (int k = 0; k < INC; k++) {
            float4 wl = Wl4[k * 32 + tx];
            float4 wr = Wr4[k * 32 + tx];
            unsigned long long wl0 = pk2(wl.x, wl.y), wl1 = pk2(wl.z, wl.w);
            unsigned long long wr0 = pk2(wr.x, wr.y), wr1 = pk2(wr.z, wr.w);
#pragma unroll
            for (int r = 0; r < 8; r++) {
                float xv = xs[ty + r * 8][k];
                unsigned long long xv2 = pk2(xv, xv);
                fma2(accL[r][0], xv2, wl0, accL[r][0]);
                fma2(accL[r][1], xv2, wl1, accL[r][1]);
                fma2(accR[r][0], xv2, wr0, accR[r][0]);
                fma2(accR[r][1], xv2, wr1, accR[r][1]);
            }
        }
        float4 blv = ((const float4*)bl)[tx];
        float4 brv = ((const float4*)br)[tx];
#pragma unroll
        for (int r = 0; r < 8; r++) {
            int row = row0 + ty + r * 8;
            if (row < NN) {
                float2 l0 = upk2(accL[r][0]), l1 = upk2(accL[r][1]);
                float2 r0 = upk2(accR[r][0]), r1 = upk2(accR[r][1]);
                uint2 lo, ro;
                lo.x = pack_h2(l0.y + blv.y, l0.x + blv.x);
                lo.y = pack_h2(l1.y + blv.w, l1.x + blv.z);
                ro.x = pack_h2(r0.y + brv.y, r0.x + brv.x);
                ro.y = pack_h2(r1.y + brv.w, r1.x + brv.z);
                g_xlh[(size_t)row * 32 + tx] = lo;
                g_xrh[(size_t)row * 32 + tx] = ro;
            }
        }
    } else if (b < GEMM_NB + DEG_NB) {
        // ---------------- deg/attr scatter part ----------------
        int e = (b - GEMM_NB) * 256 + tid;
        if (e < EE) {
            int t = ei[EE + e];
            const float4* a4 = (const float4*)&eattr[(long)e * EDIM];
            float4* dst = &((float4*)g_asum)[(long)t * 4];
#pragma unroll
            for (int q = 0; q < 4; q++) red_add_v4(&dst[q], a4[q]);
            atomicAdd(&g_deg[t], 1.f);
        }
    } else {
        // ---------------- zero part ----------------
        long i = (long)(b - GEMM_NB - DEG_NB) * 256 + tid;
        long stride = (long)ZERO_NB * 256;
        float4* acc = (float4*)g_accum;
        for (long j = i; j < (long)NN * 32; j += stride)
            acc[j] = make_float4(0.f, 0.f, 0.f, 0.f);
        for (long j = i; j < (long)NN * HH; j += stride) g_denom[j] = 0.f;
    }
}

// ---------------- kernel 2: FUSED mma edge projection + edge pass ----------
// Persistent warps grid-stride over 16-edge batches. Per batch: E(16x128) =
// attr @ W_e via 16x mma.m16n8k16 (W_e B-fragments cached in regs once per
// warp), fragments parked in padded smem (stride 68 words), then the 16
// edges are processed: gather xl/xr fp16, score, exp (no max-sub: alpha
// identical, bounded), scatter denom + exp*xl via RED.v4.
// Pure-edge batches (base+16<=EE) prefetch all 32 indices with 2 LDG and
// distribute via SHFL.
#define SMS 68   // smem row stride in words
__global__ void __launch_bounds__(256)
edge_mma_fused(const int* __restrict__ ei,
               const float* __restrict__ eattr,
               const float* __restrict__ We,
               const float* __restrict__ att) {
    __shared__ unsigned es[8][16 * SMS];
    int lane = threadIdx.x & 31;
    int w = threadIdx.x >> 5;
    unsigned* sm = es[w];
    int grp = lane >> 2, ctg = lane & 3;

    // B fragments for all 16 n-tiles (once per warp)
    unsigned b0[16], b1[16];
#pragma unroll
    for (int t = 0; t < 16; t++) {
        int col = t * 8 + grp;
        float x0 = __ldg(&We[(2 * ctg) * HO + col]);
        float x1 = __ldg(&We[(2 * ctg + 1) * HO + col]);
        float x2 = __ldg(&We[(2 * ctg + 8) * HO + col]);
        float x3 = __ldg(&We[(2 * ctg + 9) * HO + col]);
        b0[t] = pack_h2(x1, x0);
        b1[t] = pack_h2(x3, x2);
    }
    float4 av = __ldg(&((const float4*)att)[lane]);

    // consumer smem word offset for this lane's channel quad
    int pw = (lane >> 1) * 4 + 2 * (lane & 1);

    long warp0 = (long)blockIdx.x * 8 + w;
    long nwarp = (long)gridDim.x * 8;

    for (long batch = warp0; batch < NBATCH; batch += nwarp) {
        long base = batch * 16;
        bool pure = (base + 16 <= EE);

        // prefetched indices for pure batches: lanes 0-15 src, 16-31 tgt
        int idxreg = 0;
        if (pure)
            idxreg = (lane < 16) ? __ldg(&ei[base + lane])
                                 : __ldg(&ei[EE + base + lane - 16]);

        // ---- A fragments: rows base+grp (a0,a2), base+grp+8 (a1,a3) ----
        unsigned a0, a1, a2, a3;
        if (pure) {
            const float* p0 = &eattr[(base + grp) * EDIM];
            float2 lo = *(const float2*)(p0 + 2 * ctg);
            float2 hi = *(const float2*)(p0 + 2 * ctg + 8);
            a0 = pack_h2(lo.y, lo.x);
            a2 = pack_h2(hi.y, hi.x);
            const float* p1 = &eattr[(base + grp + 8) * EDIM];
            float2 lo1 = *(const float2*)(p1 + 2 * ctg);
            float2 hi1 = *(const float2*)(p1 + 2 * ctg + 8);
            a1 = pack_h2(lo1.y, lo1.x);
            a3 = pack_h2(hi1.y, hi1.x);
        } else {
            {
                long row = base + grp;
                const float* p; float inv = 1.f;
                if (row < EE) { p = &eattr[row * EDIM]; }
                else { int n = (int)(row - EE); p = &g_asum[(size_t)n * EDIM];
                       inv = 1.f / fmaxf(g_deg[n], 1.f); }
                float2 lo = *(const float2*)(p + 2 * ctg);
                float2 hi = *(const float2*)(p + 2 * ctg + 8);
                a0 = pack_h2(lo.y * inv, lo.x * inv);
                a2 = pack_h2(hi.y * inv, hi.x * inv);
            }
            {
                long row = base + grp + 8;
                const float* p; float inv = 1.f;
                if (row < EE) { p = &eattr[row * EDIM]; }
                else { int n = (int)(row - EE); p = &g_asum[(size_t)n * EDIM];
                       inv = 1.f / fmaxf(g_deg[n], 1.f); }
                float2 lo = *(const float2*)(p + 2 * ctg);
                float2 hi = *(const float2*)(p + 2 * ctg + 8);
                a1 = pack_h2(lo.y * inv, lo.x * inv);
                a3 = pack_h2(hi.y * inv, hi.x * inv);
            }
        }

        // ---- 16 mma -> smem fragments ----
        float z = 0.f;
#pragma unroll
        for (int t = 0; t < 16; t++) {
            float d0, d1, d2, d3;
            asm volatile(
                "mma.sync.aligned.m16n8k16.row.col.f32.f16.f16.f32 "
                "{%0,%1,%2,%3}, {%4,%5,%6,%7}, {%8,%9}, {%10,%10,%10,%10};"
                : "=f"(d0), "=f"(d1), "=f"(d2), "=f"(d3)
                : "r"(a0), "r"(a1), "r"(a2), "r"(a3),
                  "r"(b0[t]), "r"(b1[t]), "f"(z));
            sm[grp * SMS + t * 4 + ctg]       = pack_h2(d1, d0);
            sm[(grp + 8) * SMS + t * 4 + ctg] = pack_h2(d3, d2);
        }
        __syncwarp();

        // ---- process the 16 edges of this batch ----
#pragma unroll 4
        for (int g16 = 0; g16 < 16; g16++) {
            int s, t;
            if (pure) {
                s = __shfl_sync(0xffffffffu, idxreg, g16);
                t = __shfl_sync(0xffffffffu, idxreg, 16 + g16);
            } else {
                long ew = base + g16;
                if (ew < EE) { s = __ldg(&ei[ew]); t = __ldg(&ei[EE + ew]); }
                else         { s = t = (int)(ew - EE); }
            }

            uint2 xlh = __ldg(&g_xlh[(size_t)s * 32 + lane]);
            uint2 xrh = __ldg(&g_xrh[(size_t)t * 32 + lane]);
            float2 xl01 = __half22float2(*(__half2*)&xlh.x);
            float2 xl23 = __half22float2(*(__half2*)&xlh.y);
            float2 xr01 = __half22float2(*(__half2*)&xrh.x);
            float2 xr23 = __half22float2(*(__half2*)&xrh.y);

            uint2 ev = *(const uint2*)&sm[g16 * SMS + pw];
            float2 e01 = __half22float2(*(__half2*)&ev.x);
            float2 e23 = __half22float2(*(__half2*)&ev.y);

            float m0 = lrelu(xl01.x + xr01.x + e01.x);
            float m1 = lrelu(xl01.y + xr01.y + e01.y);
            float m2 = lrelu(xl23.x + xr23.x + e23.x);
            float m3 = lrelu(xl23.y + xr23.y + e23.y);
            float p = m0 * av.x + m1 * av.y + m2 * av.z + m3 * av.w;
            p += __shfl_xor_sync(0xffffffffu, p, 4);
            p += __shfl_xor_sync(0xffffffffu, p, 2);
            p += __shfl_xor_sync(0xffffffffu, p, 1);

            float ex = __expf(p);

            if ((lane & 7) == 0)
                atomicAdd(&g_denom[(size_t)t * HH + (lane >> 3)], ex);

            red_add_v4(&g_accum[(long)t * 32 + lane],
                       make_float4(ex * xl01.x, ex * xl01.y,
                                   ex * xl23.x, ex * xl23.y));
        }
        __syncwarp();   // protect smem before next batch overwrites
    }
}

// ---------------- kernel 3: finalize (head mean + bias + LeakyReLU) --------
__global__ void finalize_kernel(const float* __restrict__ bias,
                                float* __restrict__ out) {
    int idx = blockIdx.x * blockDim.x + threadIdx.x;
    if (idx >= NN * OUTC) return;
    int n = idx >> 5, c = idx & 31;
    const float* acc = (const float*)g_accum;
    float sum = 0.f;
#pragma unroll
    for (int hh = 0; hh < HH; hh++)
        sum += acc[(size_t)n * HO + hh * OUTC + c] / g_denom[(size_t)n * HH + hh];
    float o = sum * 0.25f + bias[c];
    out[idx] = lrelu(o);
}

// ---------------- launch ---------------------------------------------------
extern "C" void kernel_launch(void* const* d_in, const int* in_sizes, int n_in,
                              void* d_out, int out_size) {
    const float* x     = (const float*)d_in[0];
    const int*   ei    = (const int*)  d_in[1];
    const float* eattr = (const float*)d_in[2];
    const float* Wl    = (const float*)d_in[3];
    const float* bl    = (const float*)d_in[4];
    const float* Wr    = (const float*)d_in[5];
    const float* br    = (const float*)d_in[6];
    const float* We    = (const float*)d_in[7];
    const float* att   = (const float*)d_in[8];
    const float* bias  = (const float*)d_in[9];
    float* out = (float*)d_out;

    // zero the atomic-accumulated self-loop scratch via memset nodes
    void* p_asum = nullptr; cudaGetSymbolAddress(&p_asum, g_asum);
    void* p_deg  = nullptr; cudaGetSymbolAddress(&p_deg,  g_deg);
    cudaMemsetAsync(p_asum, 0, sizeof(float) * (size_t)NN * EDIM);
    cudaMemsetAsync(p_deg,  0, sizeof(float) * (size_t)NN);

    fat_prologue<<<FAT_NB, 256>>>(x, Wl, bl, Wr, br, ei, eattr);
    edge_mma_fused<<<444, 256>>>(ei, eattr, We, att);
    finalize_kernel<<<(NN * OUTC + 255) / 256, 256>>>(bias, out);
}